// round 4
// baseline (speedup 1.0000x reference)
#include <cuda_runtime.h>
#include <cuda_bf16.h>
#include <cstdint>

// ============================================================================
// out[B, OUT] = x[B, IN] @ W[OUT, IN]^T + b[OUT], fp32, 4096^3.
// Plain sm_103 target (no tcgen05) -> int8 IMMA (2x fp16 HMMA rate).
// Fixed-point: x16 = round(x*S) = 256*hi8 + lo8. Three exact s8 GEMMs:
//   out*S^2 = 65536*(xh.wh) + 256*(xh.wl + xl.wh)  [+ xl.wl dropped, ~1.9e-4]
// R4 fix: A-fragment mt=1 ldmatrix offset 2048 -> 1024 (16 rows x 64B).
// ============================================================================

#define DIM 4096

// Static device scratch (allocation-free rule: __device__ globals are allowed)
__device__ int8_t g_xh[(size_t)DIM * DIM];
__device__ int8_t g_xl[(size_t)DIM * DIM];
__device__ int8_t g_wh[(size_t)DIM * DIM];
__device__ int8_t g_wl[(size_t)DIM * DIM];

static constexpr float QSCALE = 5376.0f;
static constexpr float QCLAMP = 32384.0f;   // hi in [-126,127], lo in [-128,127]

// ----------------------------------------------------------------------------
// helpers
// ----------------------------------------------------------------------------
__device__ __forceinline__ uint32_t smem_u32(const void* p) {
    uint32_t a;
    asm("{ .reg .u64 t; cvta.to.shared.u64 t, %1; cvt.u32.u64 %0, t; }"
        : "=r"(a) : "l"(p));
    return a;
}

__device__ __forceinline__ void cp16(uint32_t dst, const void* src) {
    asm volatile("cp.async.cg.shared.global [%0], [%1], 16;"
                 :: "r"(dst), "l"(src));
}
#define CP_COMMIT() asm volatile("cp.async.commit_group;" ::: "memory")
#define CP_WAIT2()  asm volatile("cp.async.wait_group 2;"  ::: "memory")

__device__ __forceinline__ void ldm4(uint32_t* r, uint32_t addr) {
    asm volatile("ldmatrix.sync.aligned.m8n8.x4.shared.b16 {%0,%1,%2,%3}, [%4];"
                 : "=r"(r[0]), "=r"(r[1]), "=r"(r[2]), "=r"(r[3]) : "r"(addr));
}

// s8 IMMA, m16n8k32, s32 accumulate (exact)
__device__ __forceinline__ void mma_s8(int* d, const uint32_t* a, const uint32_t* b) {
    asm volatile(
        "mma.sync.aligned.m16n8k32.row.col.s32.s8.s8.s32 "
        "{%0,%1,%2,%3}, {%4,%5,%6,%7}, {%8,%9}, {%0,%1,%2,%3};"
        : "+r"(d[0]), "+r"(d[1]), "+r"(d[2]), "+r"(d[3])
        : "r"(a[0]), "r"(a[1]), "r"(a[2]), "r"(a[3]), "r"(b[0]), "r"(b[1]));
}

// ----------------------------------------------------------------------------
// Kernel 1: fp32 -> int8 hi/lo fixed-point split
// ----------------------------------------------------------------------------
__global__ void __launch_bounds__(256) convert_split(const float* __restrict__ src, int which) {
    int8_t* __restrict__ hi = which ? g_wh : g_xh;
    int8_t* __restrict__ lo = which ? g_wl : g_xl;
    const int n4 = (DIM * DIM) / 4;
    const float4* __restrict__ s4 = (const float4*)src;
    for (int i = blockIdx.x * blockDim.x + threadIdx.x; i < n4;
         i += gridDim.x * blockDim.x) {
        float4 f = s4[i];
        int a0 = __float2int_rn(fminf(fmaxf(f.x * QSCALE, -QCLAMP), QCLAMP));
        int a1 = __float2int_rn(fminf(fmaxf(f.y * QSCALE, -QCLAMP), QCLAMP));
        int a2 = __float2int_rn(fminf(fmaxf(f.z * QSCALE, -QCLAMP), QCLAMP));
        int a3 = __float2int_rn(fminf(fmaxf(f.w * QSCALE, -QCLAMP), QCLAMP));
        int h0 = (a0 + 128) >> 8, h1 = (a1 + 128) >> 8;
        int h2 = (a2 + 128) >> 8, h3 = (a3 + 128) >> 8;
        int l0 = a0 - (h0 << 8), l1 = a1 - (h1 << 8);
        int l2 = a2 - (h2 << 8), l3 = a3 - (h3 << 8);
        uint32_t ph = (h0 & 0xff) | ((h1 & 0xff) << 8) | ((h2 & 0xff) << 16) | (h3 << 24);
        uint32_t pl = (l0 & 0xff) | ((l1 & 0xff) << 8) | ((l2 & 0xff) << 16) | (l3 << 24);
        ((uint32_t*)hi)[i] = ph;
        ((uint32_t*)lo)[i] = pl;
    }
}

// ----------------------------------------------------------------------------
// Kernel 2: IMMA GEMM. BM=128 BN=128 BK=64(bytes), 4 stages, 8 warps.
// ----------------------------------------------------------------------------
static constexpr int BM = 128;
static constexpr int BN = 128;
static constexpr int BK = 64;                    // int8 elems (= bytes) per chunk
static constexpr int NK = DIM / BK;              // 64 iterations

static constexpr int TILE_B = BM * BK;           // 8192 bytes per operand tile
static constexpr int OFF_AHI = 0;
static constexpr int OFF_ALO = TILE_B;
static constexpr int OFF_BHI = 2 * TILE_B;
static constexpr int OFF_BLO = 3 * TILE_B;
static constexpr int STAGE_B = 4 * TILE_B;       // 32768
static constexpr int STAGES = 4;
static constexpr int SMEM_BYTES = STAGES * STAGE_B;  // 131072

// swizzled 16B-unit offset within a tile: row r (64B rows), unit u (0..3)
__device__ __forceinline__ uint32_t sw_off(int r, int u) {
    return (uint32_t)(r * 64 + ((u ^ ((r >> 1) & 3)) << 4));
}

__device__ __forceinline__ void load_stage(uint32_t st, int tm, int tn, int k0, int tid) {
#pragma unroll
    for (int i = 0; i < 2; i++) {
        int c = tid + i * 256;
        int r = c >> 2, u = c & 3;
        uint32_t sw = sw_off(r, u);
        size_t gx = (size_t)(tm * BM + r) * DIM + k0 + u * 16;
        size_t gw = (size_t)(tn * BN + r) * DIM + k0 + u * 16;
        cp16(st + OFF_AHI + sw, g_xh + gx);
        cp16(st + OFF_ALO + sw, g_xl + gx);
        cp16(st + OFF_BHI + sw, g_wh + gw);
        cp16(st + OFF_BLO + sw, g_wl + gw);
    }
}

__global__ void __launch_bounds__(256, 1)
gemm_kernel(const float* __restrict__ bias, float* __restrict__ out) {
    extern __shared__ char smem[];
    const uint32_t sb = smem_u32(smem);
    const int tid = threadIdx.x;
    const int wid = tid >> 5;
    const int lane = tid & 31;
    const int warp_m = wid & 3;      // 4 warps along M (32 rows each)
    const int warp_n = wid >> 2;     // 2 warps along N (64 cols each)

    // Raster: 64-CTA groups (8 M-tiles x 8 N-tiles) -> L2-friendly waves
    const int bid = blockIdx.x;
    const int g = bid >> 6;
    const int tm = (g & 3) * 8 + (bid & 7);
    const int tn = (g >> 2) * 8 + ((bid >> 3) & 7);

    // ldmatrix lane addressing (16-byte k-units; identical mapping to bf16 case)
    const int a_idx = lane >> 3;
    const int a_row = warp_m * 32 + (lane & 7) + (a_idx & 1) * 8;
    const int a_kk  = a_idx >> 1;
    const int a_sw  = (a_row >> 1) & 3;
    const int b_idx = lane >> 3;
    const int b_rr  = warp_n * 64 + (lane & 7) + (b_idx >> 1) * 8;
    const int b_kk  = b_idx & 1;
    const int b_sw  = (b_rr >> 1) & 3;

    uint32_t ua[2], ub[2];
#pragma unroll
    for (int ks = 0; ks < 2; ks++) {
        ua[ks] = (uint32_t)(((ks * 2 + a_kk) ^ a_sw) << 4);
        ub[ks] = (uint32_t)(((ks * 2 + b_kk) ^ b_sw) << 4);
    }
    const uint32_t a_base = (uint32_t)(a_row * 64);
    const uint32_t b_base = (uint32_t)(b_rr * 64);

    int acc_hh[2][8][4];   // xh.wh
    int acc_cr[2][8][4];   // xh.wl + xl.wh (both scale by 256)
#pragma unroll
    for (int mt = 0; mt < 2; mt++)
#pragma unroll
        for (int nt = 0; nt < 8; nt++)
#pragma unroll
            for (int j = 0; j < 4; j++) { acc_hh[mt][nt][j] = 0; acc_cr[mt][nt][j] = 0; }

    // Prologue: fill 3 stages
#pragma unroll
    for (int s = 0; s < STAGES - 1; s++) {
        load_stage(sb + s * STAGE_B, tm, tn, s * BK, tid);
        CP_COMMIT();
    }

    for (int kt = 0; kt < NK; kt++) {
        CP_WAIT2();
        __syncthreads();
        const uint32_t stg = sb + (kt & (STAGES - 1)) * STAGE_B;

#pragma unroll
        for (int ks = 0; ks < 2; ks++) {
            uint32_t ah[2][4], al[2][4];
            // mt tile stride = 16 rows * 64B = 1024 bytes (R4 fix: was 2048)
            ldm4(ah[0], stg + OFF_AHI + a_base + ua[ks]);
            ldm4(ah[1], stg + OFF_AHI + a_base + 1024 + ua[ks]);
            ldm4(al[0], stg + OFF_ALO + a_base + ua[ks]);
            ldm4(al[1], stg + OFF_ALO + a_base + 1024 + ua[ks]);
            uint32_t bh[4][4], bl[4][4];
#pragma unroll
            for (int p = 0; p < 4; p++) {
                ldm4(bh[p], stg + OFF_BHI + b_base + p * 1024 + ub[ks]);
                ldm4(bl[p], stg + OFF_BLO + b_base + p * 1024 + ub[ks]);
            }
#pragma unroll
            for (int mt = 0; mt < 2; mt++) {
#pragma unroll
                for (int nt = 0; nt < 8; nt++) {
                    const int p = nt >> 1, h = (nt & 1) * 2;
                    mma_s8(acc_hh[mt][nt], ah[mt], &bh[p][h]);
                    mma_s8(acc_cr[mt][nt], ah[mt], &bl[p][h]);
                    mma_s8(acc_cr[mt][nt], al[mt], &bh[p][h]);
                }
            }
        }

        const int kn = kt + STAGES - 1;
        if (kn < NK)
            load_stage(sb + (kn & (STAGES - 1)) * STAGE_B, tm, tn, kn * BK, tid);
        CP_COMMIT();   // unconditional: keeps wait_group accounting exact
    }

    // Epilogue: out = (65536*hh + 256*cr)/S^2 + bias
    const float INV = 1.0f / (QSCALE * QSCALE);
    const float S_HH = 65536.0f * INV;
    const float S_CR = 256.0f * INV;
    const int m0 = tm * BM + warp_m * 32;
    const int n0 = tn * BN + warp_n * 64;
    const int er = lane >> 2;
    const int ec = (lane & 3) * 2;
#pragma unroll
    for (int nt = 0; nt < 8; nt++) {
        const int col = n0 + nt * 8 + ec;
        const float b0 = __ldg(bias + col);
        const float b1 = __ldg(bias + col + 1);
#pragma unroll
        for (int mt = 0; mt < 2; mt++) {
            const int row = m0 + mt * 16 + er;
            float2 v0, v1;
            v0.x = fmaf((float)acc_hh[mt][nt][0], S_HH, (float)acc_cr[mt][nt][0] * S_CR) + b0;
            v0.y = fmaf((float)acc_hh[mt][nt][1], S_HH, (float)acc_cr[mt][nt][1] * S_CR) + b1;
            v1.x = fmaf((float)acc_hh[mt][nt][2], S_HH, (float)acc_cr[mt][nt][2] * S_CR) + b0;
            v1.y = fmaf((float)acc_hh[mt][nt][3], S_HH, (float)acc_cr[mt][nt][3] * S_CR) + b1;
            *(float2*)(out + (size_t)row * DIM + col) = v0;
            *(float2*)(out + (size_t)(row + 8) * DIM + col) = v1;
        }
    }
}

// ----------------------------------------------------------------------------
// kernel_launch
// ----------------------------------------------------------------------------
extern "C" void kernel_launch(void* const* d_in, const int* in_sizes, int n_in,
                              void* d_out, int out_size) {
    const float* x = (const float*)d_in[0];
    const float* W = (const float*)d_in[1];
    const float* b = (const float*)d_in[2];
    float* out = (float*)d_out;

    cudaFuncSetAttribute(gemm_kernel,
                         cudaFuncAttributeMaxDynamicSharedMemorySize, SMEM_BYTES);

    convert_split<<<4096, 256>>>(x, 0);
    convert_split<<<4096, 256>>>(W, 1);

    const int grid = (DIM / BM) * (DIM / BN);   // 1024
    gemm_kernel<<<grid, 256, SMEM_BYTES>>>(b, out);
}

// round 5
// speedup vs baseline: 6.1982x; 6.1982x over previous
#include <cuda_runtime.h>
#include <cuda_fp16.h>
#include <cstdint>

// ============================================================================
// out[B, OUT] = x[B, IN] @ W[OUT, IN]^T + b[OUT], fp32, 4096^3.
// Plain sm_103 target (no tcgen05; legacy IMMA ~6x slower than HMMA -> avoid).
// Single-pass fp16 HMMA: products exact in fp32, only input-rounding error.
// Predicted norm rel_err ~3e-4 (<1e-3).
// ============================================================================

#define DIM 4096

// Static device scratch (allocation-free rule: __device__ globals are allowed)
__device__ __half g_xh[(size_t)DIM * DIM];
__device__ __half g_wh[(size_t)DIM * DIM];

// ----------------------------------------------------------------------------
// helpers
// ----------------------------------------------------------------------------
__device__ __forceinline__ uint32_t smem_u32(const void* p) {
    uint32_t a;
    asm("{ .reg .u64 t; cvta.to.shared.u64 t, %1; cvt.u32.u64 %0, t; }"
        : "=r"(a) : "l"(p));
    return a;
}

__device__ __forceinline__ void cp16(uint32_t dst, const void* src) {
    asm volatile("cp.async.cg.shared.global [%0], [%1], 16;"
                 :: "r"(dst), "l"(src));
}
#define CP_COMMIT() asm volatile("cp.async.commit_group;" ::: "memory")
#define CP_WAIT()   asm volatile("cp.async.wait_group 6;"  ::: "memory")

__device__ __forceinline__ void ldm4(uint32_t* r, uint32_t addr) {
    asm volatile("ldmatrix.sync.aligned.m8n8.x4.shared.b16 {%0,%1,%2,%3}, [%4];"
                 : "=r"(r[0]), "=r"(r[1]), "=r"(r[2]), "=r"(r[3]) : "r"(addr));
}

__device__ __forceinline__ void mma16816(float* d, const uint32_t* a, const uint32_t* b) {
    asm volatile(
        "mma.sync.aligned.m16n8k16.row.col.f32.f16.f16.f32 "
        "{%0,%1,%2,%3}, {%4,%5,%6,%7}, {%8,%9}, {%0,%1,%2,%3};"
        : "+f"(d[0]), "+f"(d[1]), "+f"(d[2]), "+f"(d[3])
        : "r"(a[0]), "r"(a[1]), "r"(a[2]), "r"(a[3]), "r"(b[0]), "r"(b[1]));
}

// ----------------------------------------------------------------------------
// Kernel 1: fp32 -> fp16 (both matrices in one launch)
// ----------------------------------------------------------------------------
__global__ void __launch_bounds__(256)
convert_half(const float* __restrict__ x, const float* __restrict__ W) {
    const int n4 = (DIM * DIM) / 4;      // float4 chunks per matrix
    for (int i = blockIdx.x * blockDim.x + threadIdx.x; i < 2 * n4;
         i += gridDim.x * blockDim.x) {
        const bool isw = i >= n4;
        const int j = isw ? i - n4 : i;
        float4 f = ((const float4*)(isw ? W : x))[j];
        __half2 h0 = __floats2half2_rn(f.x, f.y);
        __half2 h1 = __floats2half2_rn(f.z, f.w);
        uint2 pk;
        pk.x = *(const uint32_t*)&h0;
        pk.y = *(const uint32_t*)&h1;
        ((uint2*)(isw ? g_wh : g_xh))[j] = pk;
    }
}

// ----------------------------------------------------------------------------
// Kernel 2: fp16 HMMA GEMM. BM=128 BN=128 BK=32, 8 stages, 8 warps.
// ----------------------------------------------------------------------------
static constexpr int BM = 128;
static constexpr int BN = 128;
static constexpr int BK = 32;                    // fp16 elems (64B rows)
static constexpr int NK = DIM / BK;              // 128 iterations

static constexpr int TILE_B = BM * BK * 2;       // 8192 bytes per operand tile
static constexpr int OFF_A = 0;
static constexpr int OFF_B = TILE_B;
static constexpr int STAGE_B = 2 * TILE_B;       // 16384
static constexpr int STAGES = 8;
static constexpr int SMEM_BYTES = STAGES * STAGE_B;  // 131072

// swizzled 16B-unit offset within a tile: row r (64B rows), unit u (0..3)
__device__ __forceinline__ uint32_t sw_off(int r, int u) {
    return (uint32_t)(r * 64 + ((u ^ ((r >> 1) & 3)) << 4));
}

__device__ __forceinline__ void load_stage(uint32_t st, int tm, int tn, int k0, int tid) {
#pragma unroll
    for (int i = 0; i < 2; i++) {
        int c = tid + i * 256;
        int r = c >> 2, u = c & 3;
        uint32_t sw = sw_off(r, u);
        size_t gx = (size_t)(tm * BM + r) * DIM + k0 + u * 8;
        size_t gw = (size_t)(tn * BN + r) * DIM + k0 + u * 8;
        cp16(st + OFF_A + sw, g_xh + gx);
        cp16(st + OFF_B + sw, g_wh + gw);
    }
}

__global__ void __launch_bounds__(256, 1)
gemm_kernel(const float* __restrict__ bias, float* __restrict__ out) {
    extern __shared__ char smem[];
    const uint32_t sb = smem_u32(smem);
    const int tid = threadIdx.x;
    const int wid = tid >> 5;
    const int lane = tid & 31;
    const int warp_m = wid & 3;      // 4 warps along M (32 rows each)
    const int warp_n = wid >> 2;     // 2 warps along N (64 cols each)

    // Raster: 64-CTA groups (8 M-tiles x 8 N-tiles) -> L2-friendly waves
    const int bid = blockIdx.x;
    const int g = bid >> 6;
    const int tm = (g & 3) * 8 + (bid & 7);
    const int tn = (g >> 2) * 8 + ((bid >> 3) & 7);

    // ldmatrix lane addressing (identical to proven round-2 mapping)
    const int a_idx = lane >> 3;
    const int a_row = warp_m * 32 + (lane & 7) + (a_idx & 1) * 8;
    const int a_kk  = a_idx >> 1;
    const int a_sw  = (a_row >> 1) & 3;
    const int b_idx = lane >> 3;
    const int b_rr  = warp_n * 64 + (lane & 7) + (b_idx >> 1) * 8;
    const int b_kk  = b_idx & 1;
    const int b_sw  = (b_rr >> 1) & 3;

    uint32_t ua[2], ub[2];
#pragma unroll
    for (int ks = 0; ks < 2; ks++) {
        ua[ks] = (uint32_t)(((ks * 2 + a_kk) ^ a_sw) << 4);
        ub[ks] = (uint32_t)(((ks * 2 + b_kk) ^ b_sw) << 4);
    }
    const uint32_t a_base = (uint32_t)(a_row * 64);
    const uint32_t b_base = (uint32_t)(b_rr * 64);

    float acc[2][8][4];
#pragma unroll
    for (int mt = 0; mt < 2; mt++)
#pragma unroll
        for (int nt = 0; nt < 8; nt++)
#pragma unroll
            for (int j = 0; j < 4; j++) acc[mt][nt][j] = 0.f;

    // Prologue: fill STAGES-1 stages
#pragma unroll
    for (int s = 0; s < STAGES - 1; s++) {
        load_stage(sb + s * STAGE_B, tm, tn, s * BK, tid);
        CP_COMMIT();
    }

    for (int kt = 0; kt < NK; kt++) {
        CP_WAIT();
        __syncthreads();
        const uint32_t stg = sb + (kt & (STAGES - 1)) * STAGE_B;

#pragma unroll
        for (int ks = 0; ks < 2; ks++) {
            uint32_t a[2][4];
            ldm4(a[0], stg + OFF_A + a_base + ua[ks]);
            ldm4(a[1], stg + OFF_A + a_base + 1024 + ua[ks]);
            uint32_t b[4][4];
#pragma unroll
            for (int p = 0; p < 4; p++)
                ldm4(b[p], stg + OFF_B + b_base + p * 1024 + ub[ks]);
#pragma unroll
            for (int mt = 0; mt < 2; mt++) {
#pragma unroll
                for (int nt = 0; nt < 8; nt++) {
                    const int p = nt >> 1, h = (nt & 1) * 2;
                    mma16816(acc[mt][nt], a[mt], &b[p][h]);
                }
            }
        }

        const int kn = kt + STAGES - 1;
        if (kn < NK)
            load_stage(sb + (kn & (STAGES - 1)) * STAGE_B, tm, tn, kn * BK, tid);
        CP_COMMIT();   // unconditional: keeps wait_group accounting exact
    }

    // Epilogue: add bias, store fp32
    const int m0 = tm * BM + warp_m * 32;
    const int n0 = tn * BN + warp_n * 64;
    const int er = lane >> 2;
    const int ec = (lane & 3) * 2;
#pragma unroll
    for (int nt = 0; nt < 8; nt++) {
        const int col = n0 + nt * 8 + ec;
        const float b0 = __ldg(bias + col);
        const float b1 = __ldg(bias + col + 1);
#pragma unroll
        for (int mt = 0; mt < 2; mt++) {
            const int row = m0 + mt * 16 + er;
            float2 v0 = make_float2(acc[mt][nt][0] + b0, acc[mt][nt][1] + b1);
            float2 v1 = make_float2(acc[mt][nt][2] + b0, acc[mt][nt][3] + b1);
            *(float2*)(out + (size_t)row * DIM + col) = v0;
            *(float2*)(out + (size_t)(row + 8) * DIM + col) = v1;
        }
    }
}

// ----------------------------------------------------------------------------
// kernel_launch
// ----------------------------------------------------------------------------
extern "C" void kernel_launch(void* const* d_in, const int* in_sizes, int n_in,
                              void* d_out, int out_size) {
    const float* x = (const float*)d_in[0];
    const float* W = (const float*)d_in[1];
    const float* b = (const float*)d_in[2];
    float* out = (float*)d_out;

    cudaFuncSetAttribute(gemm_kernel,
                         cudaFuncAttributeMaxDynamicSharedMemorySize, SMEM_BYTES);

    convert_half<<<8192, 256>>>(x, W);

    const int grid = (DIM / BM) * (DIM / BN);   // 1024
    gemm_kernel<<<grid, 256, SMEM_BYTES>>>(b, out);
}

// round 6
// speedup vs baseline: 6.7650x; 1.0914x over previous
#include <cuda_runtime.h>
#include <cuda_fp16.h>
#include <cstdint>

// ============================================================================
// out[B, OUT] = x[B, IN] @ W[OUT, IN]^T + b[OUT], fp32, 4096^3.
// Plain sm_103 target -> fp16 HMMA single pass (products exact in fp32).
// R6: CTA tile 256x128, warp tile 64x64 (MMA:LDS ratio 2.67 -> 4.0),
//     5-stage cp.async ring. Attacks tensor=52.8% starvation seen in R5.
// ============================================================================

#define DIM 4096

__device__ __half g_xh[(size_t)DIM * DIM];
__device__ __half g_wh[(size_t)DIM * DIM];

// ----------------------------------------------------------------------------
// helpers
// ----------------------------------------------------------------------------
__device__ __forceinline__ uint32_t smem_u32(const void* p) {
    uint32_t a;
    asm("{ .reg .u64 t; cvta.to.shared.u64 t, %1; cvt.u32.u64 %0, t; }"
        : "=r"(a) : "l"(p));
    return a;
}

__device__ __forceinline__ void cp16(uint32_t dst, const void* src) {
    asm volatile("cp.async.cg.shared.global [%0], [%1], 16;"
                 :: "r"(dst), "l"(src));
}
#define CP_COMMIT() asm volatile("cp.async.commit_group;" ::: "memory")
#define CP_WAIT()   asm volatile("cp.async.wait_group 3;"  ::: "memory")

__device__ __forceinline__ void ldm4(uint32_t* r, uint32_t addr) {
    asm volatile("ldmatrix.sync.aligned.m8n8.x4.shared.b16 {%0,%1,%2,%3}, [%4];"
                 : "=r"(r[0]), "=r"(r[1]), "=r"(r[2]), "=r"(r[3]) : "r"(addr));
}

__device__ __forceinline__ void mma16816(float* d, const uint32_t* a, const uint32_t* b) {
    asm volatile(
        "mma.sync.aligned.m16n8k16.row.col.f32.f16.f16.f32 "
        "{%0,%1,%2,%3}, {%4,%5,%6,%7}, {%8,%9}, {%0,%1,%2,%3};"
        : "+f"(d[0]), "+f"(d[1]), "+f"(d[2]), "+f"(d[3])
        : "r"(a[0]), "r"(a[1]), "r"(a[2]), "r"(a[3]), "r"(b[0]), "r"(b[1]));
}

// ----------------------------------------------------------------------------
// Kernel 1: fp32 -> fp16 (both matrices in one launch)
// ----------------------------------------------------------------------------
__global__ void __launch_bounds__(256)
convert_half(const float* __restrict__ x, const float* __restrict__ W) {
    const int n4 = (DIM * DIM) / 4;
    for (int i = blockIdx.x * blockDim.x + threadIdx.x; i < 2 * n4;
         i += gridDim.x * blockDim.x) {
        const bool isw = i >= n4;
        const int j = isw ? i - n4 : i;
        float4 f = ((const float4*)(isw ? W : x))[j];
        __half2 h0 = __floats2half2_rn(f.x, f.y);
        __half2 h1 = __floats2half2_rn(f.z, f.w);
        uint2 pk;
        pk.x = *(const uint32_t*)&h0;
        pk.y = *(const uint32_t*)&h1;
        ((uint2*)(isw ? g_wh : g_xh))[j] = pk;
    }
}

// ----------------------------------------------------------------------------
// Kernel 2: fp16 HMMA GEMM. BM=256 BN=128 BK=32, 5 stages, 8 warps (4x2).
// ----------------------------------------------------------------------------
static constexpr int BM = 256;
static constexpr int BN = 128;
static constexpr int BK = 32;                    // fp16 elems (64B rows)
static constexpr int NK = DIM / BK;              // 128 iterations

static constexpr int A_B = BM * BK * 2;          // 16384
static constexpr int B_B = BN * BK * 2;          // 8192
static constexpr int OFF_A = 0;
static constexpr int OFF_B = A_B;
static constexpr int STAGE_B = A_B + B_B;        // 24576
static constexpr int STAGES = 5;
static constexpr int SMEM_BYTES = STAGES * STAGE_B;  // 122880

// swizzled 16B-unit offset within a tile: row r (64B rows), unit u (0..3)
__device__ __forceinline__ uint32_t sw_off(int r, int u) {
    return (uint32_t)(r * 64 + ((u ^ ((r >> 1) & 3)) << 4));
}

// 1536 cp16 per stage / 256 threads = 6 each (4 for A, 2 for B)
__device__ __forceinline__ void load_stage(uint32_t st, int tm, int tn, int k0, int tid) {
#pragma unroll
    for (int i = 0; i < 4; i++) {
        int c = tid + i * 256;
        int r = c >> 2, u = c & 3;
        uint32_t sw = sw_off(r, u);
        size_t gx = (size_t)(tm * BM + r) * DIM + k0 + u * 8;
        cp16(st + OFF_A + sw, g_xh + gx);
    }
#pragma unroll
    for (int i = 0; i < 2; i++) {
        int c = tid + i * 256;
        int r = c >> 2, u = c & 3;
        uint32_t sw = sw_off(r, u);
        size_t gw = (size_t)(tn * BN + r) * DIM + k0 + u * 8;
        cp16(st + OFF_B + sw, g_wh + gw);
    }
}

__global__ void __launch_bounds__(256, 1)
gemm_kernel(const float* __restrict__ bias, float* __restrict__ out) {
    extern __shared__ char smem[];
    const uint32_t sb = smem_u32(smem);
    const int tid = threadIdx.x;
    const int wid = tid >> 5;
    const int lane = tid & 31;
    const int warp_m = wid & 3;      // 4 warps along M (64 rows each)
    const int warp_n = wid >> 2;     // 2 warps along N (64 cols each)

    // Grid: 16 tm x 32 tn = 512 CTAs. tn-major within a wave -> A shared in L2.
    const int bid = blockIdx.x;
    const int tm = bid & 15;
    const int tn = bid >> 4;

    // ldmatrix lane addressing (same mapping as proven kernels; A spans 64 rows)
    const int a_idx = lane >> 3;
    const int a_row = warp_m * 64 + (lane & 7) + (a_idx & 1) * 8;
    const int a_kk  = a_idx >> 1;
    const int a_sw  = (a_row >> 1) & 3;
    const int b_idx = lane >> 3;
    const int b_rr  = warp_n * 64 + (lane & 7) + (b_idx >> 1) * 8;
    const int b_kk  = b_idx & 1;
    const int b_sw  = (b_rr >> 1) & 3;

    uint32_t ua[2], ub[2];
#pragma unroll
    for (int ks = 0; ks < 2; ks++) {
        ua[ks] = (uint32_t)(((ks * 2 + a_kk) ^ a_sw) << 4);
        ub[ks] = (uint32_t)(((ks * 2 + b_kk) ^ b_sw) << 4);
    }
    const uint32_t a_base = (uint32_t)(a_row * 64);
    const uint32_t b_base = (uint32_t)(b_rr * 64);

    float acc[4][8][4];
#pragma unroll
    for (int mt = 0; mt < 4; mt++)
#pragma unroll
        for (int nt = 0; nt < 8; nt++)
#pragma unroll
            for (int j = 0; j < 4; j++) acc[mt][nt][j] = 0.f;

    // Prologue: fill STAGES-1 = 4 stages
#pragma unroll
    for (int s = 0; s < STAGES - 1; s++) {
        load_stage(sb + s * STAGE_B, tm, tn, s * BK, tid);
        CP_COMMIT();
    }

    int s_cur = 0;                  // stage of iteration kt
    int s_nxt = STAGES - 1;         // stage receiving kt + STAGES-1
    for (int kt = 0; kt < NK; kt++) {
        CP_WAIT();
        __syncthreads();
        const uint32_t stg = sb + s_cur * STAGE_B;

#pragma unroll
        for (int ks = 0; ks < 2; ks++) {
            uint32_t a[4][4];
#pragma unroll
            for (int mt = 0; mt < 4; mt++)
                ldm4(a[mt], stg + OFF_A + a_base + mt * 1024 + ua[ks]);
            uint32_t b[4][4];
#pragma unroll
            for (int p = 0; p < 4; p++)
                ldm4(b[p], stg + OFF_B + b_base + p * 1024 + ub[ks]);
#pragma unroll
            for (int mt = 0; mt < 4; mt++) {
#pragma unroll
                for (int nt = 0; nt < 8; nt++) {
                    const int p = nt >> 1, h = (nt & 1) * 2;
                    mma16816(acc[mt][nt], a[mt], &b[p][h]);
                }
            }
        }

        const int kn = kt + STAGES - 1;
        if (kn < NK)
            load_stage(sb + s_nxt * STAGE_B, tm, tn, kn * BK, tid);
        CP_COMMIT();   // unconditional: keeps wait_group accounting exact

        if (++s_cur == STAGES) s_cur = 0;
        if (++s_nxt == STAGES) s_nxt = 0;
    }

    // Epilogue: add bias, store fp32
    const int m0 = tm * BM + warp_m * 64;
    const int n0 = tn * BN + warp_n * 64;
    const int er = lane >> 2;
    const int ec = (lane & 3) * 2;
#pragma unroll
    for (int nt = 0; nt < 8; nt++) {
        const int col = n0 + nt * 8 + ec;
        const float b0 = __ldg(bias + col);
        const float b1 = __ldg(bias + col + 1);
#pragma unroll
        for (int mt = 0; mt < 4; mt++) {
            const int row = m0 + mt * 16 + er;
            float2 v0 = make_float2(acc[mt][nt][0] + b0, acc[mt][nt][1] + b1);
            float2 v1 = make_float2(acc[mt][nt][2] + b0, acc[mt][nt][3] + b1);
            *(float2*)(out + (size_t)row * DIM + col) = v0;
            *(float2*)(out + (size_t)(row + 8) * DIM + col) = v1;
        }
    }
}

// ----------------------------------------------------------------------------
// kernel_launch
// ----------------------------------------------------------------------------
extern "C" void kernel_launch(void* const* d_in, const int* in_sizes, int n_in,
                              void* d_out, int out_size) {
    const float* x = (const float*)d_in[0];
    const float* W = (const float*)d_in[1];
    const float* b = (const float*)d_in[2];
    float* out = (float*)d_out;

    cudaFuncSetAttribute(gemm_kernel,
                         cudaFuncAttributeMaxDynamicSharedMemorySize, SMEM_BYTES);

    convert_half<<<8192, 256>>>(x, W);

    const int grid = (DIM / BM) * (DIM / BN);   // 16 * 32 = 512
    gemm_kernel<<<grid, 256, SMEM_BYTES>>>(b, out);
}